// round 1
// baseline (speedup 1.0000x reference)
#include <cuda_runtime.h>
#include <math.h>

#define BB 2
#define TT 2048
#define EE 1024
#define HH 16
#define DH 64
#define MROWS (BB*TT)   /* 4096 */

// Scratch (allocation-free rule: __device__ globals)
__device__ float g_q [MROWS*EE];
__device__ float g_k [MROWS*EE];
__device__ float g_v [MROWS*EE];
__device__ float g_ao[MROWS*EE];

// ---------------------------------------------------------------------------
// SGEMM: C[M,N] = A[M,K] @ B[K,N] (+ bias[N] if bias != nullptr)
// BM=128, BN=128, BK=16, 256 threads, 8x8 per thread. M,N,K multiples of 128/16.
// ---------------------------------------------------------------------------
__global__ __launch_bounds__(256) void sgemm_kernel(
    const float* __restrict__ A, const float* __restrict__ B,
    const float* __restrict__ bias, float* __restrict__ C,
    int M, int N, int K) {
  __shared__ float As[16][128];   // transposed: As[k][m]
  __shared__ float Bs[16][128];   // Bs[k][n]
  const int tid  = threadIdx.x;
  const int tcol = tid & 15;      // 0..15
  const int trow = tid >> 4;      // 0..15
  const int bx = blockIdx.x, by = blockIdx.y;
  const int arow  = tid >> 2;         // 0..63
  const int acol4 = (tid & 3) << 2;   // 0,4,8,12
  const int brow  = tid >> 5;         // 0..7
  const int bcol  = (tid & 31) << 2;  // 0..124
  const float* Ablk = A + (size_t)by * 128 * K;
  const float* Bblk = B + (size_t)bx * 128;

  float acc[8][8];
#pragma unroll
  for (int i = 0; i < 8; i++)
#pragma unroll
    for (int j = 0; j < 8; j++) acc[i][j] = 0.f;

  for (int k0 = 0; k0 < K; k0 += 16) {
#pragma unroll
    for (int s = 0; s < 2; s++) {
      float4 av = *(const float4*)&Ablk[(size_t)(arow + s*64) * K + k0 + acol4];
      As[acol4+0][arow + s*64] = av.x;
      As[acol4+1][arow + s*64] = av.y;
      As[acol4+2][arow + s*64] = av.z;
      As[acol4+3][arow + s*64] = av.w;
      *(float4*)&Bs[brow + s*8][bcol] =
          *(const float4*)&Bblk[(size_t)(k0 + brow + s*8) * N + bcol];
    }
    __syncthreads();
#pragma unroll
    for (int k = 0; k < 16; k++) {
      float a[8], b[8];
      *(float4*)&a[0] = *(float4*)&As[k][trow*8];
      *(float4*)&a[4] = *(float4*)&As[k][trow*8+4];
      *(float4*)&b[0] = *(float4*)&Bs[k][tcol*8];
      *(float4*)&b[4] = *(float4*)&Bs[k][tcol*8+4];
#pragma unroll
      for (int i = 0; i < 8; i++)
#pragma unroll
        for (int j = 0; j < 8; j++)
          acc[i][j] += a[i] * b[j];
    }
    __syncthreads();
  }

#pragma unroll
  for (int i = 0; i < 8; i++) {
    const size_t row = (size_t)by*128 + trow*8 + i;
#pragma unroll
    for (int j4 = 0; j4 < 2; j4++) {
      const int col = bx*128 + tcol*8 + j4*4;
      float4 r;
      r.x = acc[i][j4*4+0]; r.y = acc[i][j4*4+1];
      r.z = acc[i][j4*4+2]; r.w = acc[i][j4*4+3];
      if (bias) {
        r.x += bias[col+0]; r.y += bias[col+1];
        r.z += bias[col+2]; r.w += bias[col+3];
      }
      *(float4*)&C[row*N + col] = r;
    }
  }
}

// ---------------------------------------------------------------------------
// Flash attention (causal), fp32. One block = (b, h, 64-row q tile).
// 256 threads as 16x16; each thread owns 4 q-rows x 4 cols (of S or of Dh).
// q/k/v layout: [B*T, H*Dh] row-major.
// ---------------------------------------------------------------------------
#define QT_STRIDE 68
#define SMEM_ATTN ((3*64*QT_STRIDE + 64*64) * 4)

__global__ __launch_bounds__(256) void attn_kernel(
    const float* __restrict__ Q, const float* __restrict__ K,
    const float* __restrict__ V, float* __restrict__ O) {
  extern __shared__ float sm[];
  float* Qt = sm;                    // [64][68] transposed (d, i)
  float* Kt = Qt + 64*QT_STRIDE;     // [64][68] transposed (d, j)
  float* Ps = Kt + 64*QT_STRIDE;     // [64][68] (i, j)
  float* Vs = Ps + 64*QT_STRIDE;     // [64][64] (j, d)

  const int qt = blockIdx.x, h = blockIdx.y, b = blockIdx.z;
  const int tid = threadIdx.x;
  const int tx = tid & 15, ty = tid >> 4;
  const float scale = 0.125f;  // 1/sqrt(64)
  const size_t base = (size_t)b * TT * EE + (size_t)h * DH;
  const int q0 = qt * 64;

  // Load Q tile transposed into smem
  for (int idx = tid; idx < 64*16; idx += 256) {
    const int r = idx >> 4, c4 = (idx & 15) << 2;
    float4 qv = *(const float4*)&Q[base + (size_t)(q0 + r) * EE + c4];
    Qt[(c4+0)*QT_STRIDE + r] = qv.x;
    Qt[(c4+1)*QT_STRIDE + r] = qv.y;
    Qt[(c4+2)*QT_STRIDE + r] = qv.z;
    Qt[(c4+3)*QT_STRIDE + r] = qv.w;
  }

  float m[4], l[4], o[4][4];
#pragma unroll
  for (int r = 0; r < 4; r++) {
    m[r] = -1e30f; l[r] = 0.f;
#pragma unroll
    for (int c = 0; c < 4; c++) o[r][c] = 0.f;
  }
  __syncthreads();

  for (int kt = 0; kt <= qt; kt++) {
    const int k0 = kt * 64;
    // Load K (transposed) and V (natural)
    for (int idx = tid; idx < 64*16; idx += 256) {
      const int r = idx >> 4, c4 = (idx & 15) << 2;
      float4 kv = *(const float4*)&K[base + (size_t)(k0 + r) * EE + c4];
      Kt[(c4+0)*QT_STRIDE + r] = kv.x;
      Kt[(c4+1)*QT_STRIDE + r] = kv.y;
      Kt[(c4+2)*QT_STRIDE + r] = kv.z;
      Kt[(c4+3)*QT_STRIDE + r] = kv.w;
      *(float4*)&Vs[r*64 + c4] = *(const float4*)&V[base + (size_t)(k0 + r) * EE + c4];
    }
    __syncthreads();

    // S = Q K^T (scaled), 4x4 per thread
    float s[4][4];
#pragma unroll
    for (int r = 0; r < 4; r++)
#pragma unroll
      for (int c = 0; c < 4; c++) s[r][c] = 0.f;
#pragma unroll 8
    for (int d = 0; d < 64; d++) {
      float4 qv = *(float4*)&Qt[d*QT_STRIDE + ty*4];
      float4 kv = *(float4*)&Kt[d*QT_STRIDE + tx*4];
      const float qa[4] = {qv.x, qv.y, qv.z, qv.w};
      const float ka[4] = {kv.x, kv.y, kv.z, kv.w};
#pragma unroll
      for (int r = 0; r < 4; r++)
#pragma unroll
        for (int c = 0; c < 4; c++)
          s[r][c] += qa[r] * ka[c];
    }
    const bool diag = (kt == qt);
#pragma unroll
    for (int r = 0; r < 4; r++)
#pragma unroll
      for (int c = 0; c < 4; c++) {
        s[r][c] *= scale;
        if (diag && (tx*4 + c > ty*4 + r)) s[r][c] = -1e30f;
      }

    // Online softmax update (row reductions over 16 tx lanes)
#pragma unroll
    for (int r = 0; r < 4; r++) {
      float tm = fmaxf(fmaxf(s[r][0], s[r][1]), fmaxf(s[r][2], s[r][3]));
#pragma unroll
      for (int off = 8; off; off >>= 1)
        tm = fmaxf(tm, __shfl_xor_sync(0xffffffffu, tm, off));
      const float mn = fmaxf(m[r], tm);
      const float f = __expf(m[r] - mn);
      float rs = 0.f;
#pragma unroll
      for (int c = 0; c < 4; c++) {
        const float p = __expf(s[r][c] - mn);
        s[r][c] = p;
        rs += p;
      }
#pragma unroll
      for (int off = 8; off; off >>= 1)
        rs += __shfl_xor_sync(0xffffffffu, rs, off);
      l[r] = l[r] * f + rs;
      m[r] = mn;
#pragma unroll
      for (int c = 0; c < 4; c++) o[r][c] *= f;
      *(float4*)&Ps[(ty*4 + r)*QT_STRIDE + tx*4] =
          make_float4(s[r][0], s[r][1], s[r][2], s[r][3]);
    }
    __syncthreads();

    // O += P @ V
#pragma unroll 4
    for (int j = 0; j < 64; j++) {
      float4 vv = *(float4*)&Vs[j*64 + tx*4];
      const float va[4] = {vv.x, vv.y, vv.z, vv.w};
      const float p0 = Ps[(ty*4+0)*QT_STRIDE + j];
      const float p1 = Ps[(ty*4+1)*QT_STRIDE + j];
      const float p2 = Ps[(ty*4+2)*QT_STRIDE + j];
      const float p3 = Ps[(ty*4+3)*QT_STRIDE + j];
#pragma unroll
      for (int c = 0; c < 4; c++) {
        o[0][c] += p0 * va[c];
        o[1][c] += p1 * va[c];
        o[2][c] += p2 * va[c];
        o[3][c] += p3 * va[c];
      }
    }
    __syncthreads();
  }

  // Normalize and write out
#pragma unroll
  for (int r = 0; r < 4; r++) {
    const float inv = 1.f / l[r];
    float4 w = make_float4(o[r][0]*inv, o[r][1]*inv, o[r][2]*inv, o[r][3]*inv);
    *(float4*)&O[base + (size_t)(q0 + ty*4 + r) * EE + tx*4] = w;
  }
}

// ---------------------------------------------------------------------------
extern "C" void kernel_launch(void* const* d_in, const int* in_sizes, int n_in,
                              void* d_out, int out_size) {
  const float* x  = (const float*)d_in[0];
  const float* Wq = (const float*)d_in[1];
  const float* Wk = (const float*)d_in[2];
  const float* Wv = (const float*)d_in[3];
  const float* Wo = (const float*)d_in[4];
  const float* bo = (const float*)d_in[5];
  float* out = (float*)d_out;

  float *q, *k, *v, *ao;
  cudaGetSymbolAddress((void**)&q,  g_q);
  cudaGetSymbolAddress((void**)&k,  g_k);
  cudaGetSymbolAddress((void**)&v,  g_v);
  cudaGetSymbolAddress((void**)&ao, g_ao);

  cudaFuncSetAttribute(attn_kernel,
                       cudaFuncAttributeMaxDynamicSharedMemorySize, SMEM_ATTN);

  dim3 ggrid(EE/128, MROWS/128);   // (8, 32)
  sgemm_kernel<<<ggrid, 256>>>(x, Wq, nullptr, q, MROWS, EE, EE);
  sgemm_kernel<<<ggrid, 256>>>(x, Wk, nullptr, k, MROWS, EE, EE);
  sgemm_kernel<<<ggrid, 256>>>(x, Wv, nullptr, v, MROWS, EE, EE);

  dim3 agrid(TT/64, HH, BB);       // (32, 16, 2)
  attn_kernel<<<agrid, 256, SMEM_ATTN>>>(q, k, v, ao);

  sgemm_kernel<<<ggrid, 256>>>(ao, Wo, bo, out, MROWS, EE, EE);
}

// round 3
// speedup vs baseline: 1.3752x; 1.3752x over previous
#include <cuda_runtime.h>
#include <cuda_bf16.h>
#include <math.h>
#include <stdint.h>

#define BB 2
#define TT 2048
#define EE 1024
#define HH 16
#define DH 64
#define MROWS (BB*TT)   /* 4096 */

// ---------------- scratch (__device__ globals; no allocs allowed) ----------
__device__ __align__(1024) float g_q [MROWS*EE];
__device__ __align__(1024) float g_k [MROWS*EE];
__device__ __align__(1024) float g_v [MROWS*EE];
__device__ __align__(1024) float g_ao[MROWS*EE];
__device__ __align__(1024) __nv_bfloat16 g_xh [MROWS*EE];
__device__ __align__(1024) __nv_bfloat16 g_xl [MROWS*EE];
__device__ __align__(1024) __nv_bfloat16 g_aoh[MROWS*EE];
__device__ __align__(1024) __nv_bfloat16 g_aol[MROWS*EE];
__device__ __align__(1024) __nv_bfloat16 g_wth[4*EE*EE];  // W^T hi  [N,K] per weight
__device__ __align__(1024) __nv_bfloat16 g_wtl[4*EE*EE];  // W^T lo

// ---------------- PTX helpers (baseline ISA only: sm_80-level) -------------
__device__ __forceinline__ uint32_t smem_to_u32(const void* p) {
  uint32_t a;
  asm("{ .reg .u64 t; cvta.to.shared.u64 t, %1; cvt.u32.u64 %0, t; }"
      : "=r"(a) : "l"(p));
  return a;
}
__device__ __forceinline__ void cpa16(uint32_t d, const void* s) {
  asm volatile("cp.async.cg.shared.global [%0], [%1], 16;" :: "r"(d), "l"(s) : "memory");
}
#define CP_COMMIT() asm volatile("cp.async.commit_group;" ::: "memory")
#define CP_WAIT(n)  asm volatile("cp.async.wait_group %0;" :: "n"(n) : "memory")

#define HMMA16816(d, a0, a1, a2, a3, b0, b1)                                   \
  asm volatile("mma.sync.aligned.m16n8k16.row.col.f32.bf16.bf16.f32 "          \
    "{%0,%1,%2,%3}, {%4,%5,%6,%7}, {%8,%9}, {%0,%1,%2,%3};"                    \
    : "+f"((d)[0]), "+f"((d)[1]), "+f"((d)[2]), "+f"((d)[3])                   \
    : "r"(a0), "r"(a1), "r"(a2), "r"(a3), "r"(b0), "r"(b1))

// ---------------------------------------------------------------------------
// HMMA GEMM: C[4096,1024] = A[4096,1024] @ B^T (+ bias)
// A: bf16 hi/lo [M,K] row-major. B: bf16 hi/lo [N,K] row-major (pre-transposed W).
// CTA 128x128, 8 warps (warp tile 64x32), BK=32, 2-stage cp.async pipeline.
// 3-pass split precision: Ah*Bh + Ah*Bl + Al*Bh, fp32 accum.
// ---------------------------------------------------------------------------
#define RS   80          /* smem row stride bytes (32 bf16 + 8 pad) */
#define MAT  (128*RS)    /* 10240 B per matrix tile */
#define STG  (4*MAT)     /* 40960 B per stage */
#define MM_SMEM (2*STG)  /* 81920 B */
#define KT   (EE/32)     /* 32 k-iterations */

__global__ __launch_bounds__(256) void mm_hmma(
    const __nv_bfloat16* __restrict__ Ah, const __nv_bfloat16* __restrict__ Al,
    const __nv_bfloat16* __restrict__ Bh, const __nv_bfloat16* __restrict__ Bl,
    float* __restrict__ C, const float* __restrict__ bias) {
  extern __shared__ char smg[];
  const int tid = threadIdx.x, wid = tid >> 5, lane = tid & 31;
  const int g = lane >> 2, tg = lane & 3;
  const int m0 = blockIdx.y * 128, n0 = blockIdx.x * 128;
  const int wm = (wid & 1) * 64, wn = (wid >> 1) * 32;
  const uint32_t sbase = smem_to_u32(smg);

  // ---- gmem load base for this thread (2x16B chunks per matrix per stage)
  const int lrow = tid >> 1;            // 0..127
  const int lch  = (tid & 1) * 2;       // chunk 0 or 2 (of 4 x 16B per row)
  const __nv_bfloat16* pAh = Ah + (size_t)(m0 + lrow) * EE + lch * 8;
  const __nv_bfloat16* pAl = Al + (size_t)(m0 + lrow) * EE + lch * 8;
  const __nv_bfloat16* pBh = Bh + (size_t)(n0 + lrow) * EE + lch * 8;
  const __nv_bfloat16* pBl = Bl + (size_t)(n0 + lrow) * EE + lch * 8;
  const uint32_t dbase = sbase + lrow * RS + lch * 16;

  float acc[4][4][4];
#pragma unroll
  for (int i = 0; i < 4; i++)
#pragma unroll
    for (int j = 0; j < 4; j++)
#pragma unroll
      for (int c = 0; c < 4; c++) acc[i][j][c] = 0.f;

  // ---- prologue: stage 0 loads k0=0
  {
    const uint32_t d = dbase;
    cpa16(d,             pAh); cpa16(d + 16,            pAh + 8);
    cpa16(d + MAT,       pAl); cpa16(d + MAT + 16,      pAl + 8);
    cpa16(d + 2*MAT,     pBh); cpa16(d + 2*MAT + 16,    pBh + 8);
    cpa16(d + 3*MAT,     pBl); cpa16(d + 3*MAT + 16,    pBl + 8);
    CP_COMMIT();
  }

  for (int it = 0; it < KT; it++) {
    if (it + 1 < KT) {
      const int k0 = (it + 1) * 32;
      const uint32_t d = dbase + ((it + 1) & 1) * STG;
      cpa16(d,          pAh + k0); cpa16(d + 16,         pAh + k0 + 8);
      cpa16(d + MAT,    pAl + k0); cpa16(d + MAT + 16,   pAl + k0 + 8);
      cpa16(d + 2*MAT,  pBh + k0); cpa16(d + 2*MAT + 16, pBh + k0 + 8);
      cpa16(d + 3*MAT,  pBl + k0); cpa16(d + 3*MAT + 16, pBl + k0 + 8);
      CP_COMMIT();
      CP_WAIT(1);
    } else {
      CP_WAIT(0);
    }
    __syncthreads();

    const char* stb = smg + (it & 1) * STG;
#pragma unroll
    for (int pass = 0; pass < 3; pass++) {
      const char* Abase = stb + (pass == 2 ? MAT : 0);
      const char* Bbase = stb + 2 * MAT + (pass == 1 ? MAT : 0);
#pragma unroll
      for (int ks = 0; ks < 2; ks++) {
        uint32_t b0[4], b1[4];
#pragma unroll
        for (int j = 0; j < 4; j++) {
          const char* bp = Bbase + (wn + j * 8 + g) * RS + ks * 32 + tg * 4;
          b0[j] = *(const uint32_t*)bp;
          b1[j] = *(const uint32_t*)(bp + 16);
        }
#pragma unroll
        for (int i = 0; i < 4; i++) {
          const char* ap = Abase + (wm + i * 16 + g) * RS + ks * 32 + tg * 4;
          const uint32_t a0 = *(const uint32_t*)ap;
          const uint32_t a1 = *(const uint32_t*)(ap + 8 * RS);
          const uint32_t a2 = *(const uint32_t*)(ap + 16);
          const uint32_t a3 = *(const uint32_t*)(ap + 8 * RS + 16);
#pragma unroll
          for (int j = 0; j < 4; j++)
            HMMA16816(acc[i][j], a0, a1, a2, a3, b0[j], b1[j]);
        }
      }
    }
    __syncthreads();
  }

  // ---- epilogue
#pragma unroll
  for (int i = 0; i < 4; i++) {
    const int r0 = m0 + wm + i * 16 + g;
#pragma unroll
    for (int j = 0; j < 4; j++) {
      const int c = n0 + wn + j * 8 + tg * 2;
      float bx = 0.f, by = 0.f;
      if (bias) { bx = bias[c]; by = bias[c + 1]; }
      float2 v0 = make_float2(acc[i][j][0] + bx, acc[i][j][1] + by);
      float2 v1 = make_float2(acc[i][j][2] + bx, acc[i][j][3] + by);
      *(float2*)&C[(size_t)r0 * EE + c]       = v0;
      *(float2*)&C[(size_t)(r0 + 8) * EE + c] = v1;
    }
  }
}

// ---------------------------------------------------------------------------
// fp32 -> bf16 hi/lo split (elementwise, vectorized)
// ---------------------------------------------------------------------------
__global__ __launch_bounds__(256) void convert_split_kernel(
    const float4* __restrict__ in, ushort4* __restrict__ hi,
    ushort4* __restrict__ lo, int n4) {
  const int i = blockIdx.x * 256 + threadIdx.x;
  if (i >= n4) return;
  const float4 v = in[i];
  ushort4 h, l;
  __nv_bfloat16 b;
  b = __float2bfloat16(v.x); h.x = __bfloat16_as_ushort(b);
  l.x = __bfloat16_as_ushort(__float2bfloat16(v.x - __bfloat162float(b)));
  b = __float2bfloat16(v.y); h.y = __bfloat16_as_ushort(b);
  l.y = __bfloat16_as_ushort(__float2bfloat16(v.y - __bfloat162float(b)));
  b = __float2bfloat16(v.z); h.z = __bfloat16_as_ushort(b);
  l.z = __bfloat16_as_ushort(__float2bfloat16(v.z - __bfloat162float(b)));
  b = __float2bfloat16(v.w); h.w = __bfloat16_as_ushort(b);
  l.w = __bfloat16_as_ushort(__float2bfloat16(v.w - __bfloat162float(b)));
  hi[i] = h; lo[i] = l;
}

// ---------------------------------------------------------------------------
// W[K=1024,N=1024] fp32 -> Wt hi/lo [N,K] bf16 (tiled transpose + split)
// ---------------------------------------------------------------------------
__global__ __launch_bounds__(256) void transpose_split_kernel(
    const float* __restrict__ W, __nv_bfloat16* __restrict__ th,
    __nv_bfloat16* __restrict__ tl) {
  __shared__ float t[32][33];
  const int n0 = blockIdx.x * 32, k0 = blockIdx.y * 32;
  const int tx = threadIdx.x & 31, ty = threadIdx.x >> 5;  // 32 x 8
  for (int r = ty; r < 32; r += 8)
    t[r][tx] = W[(size_t)(k0 + r) * EE + n0 + tx];
  __syncthreads();
  for (int r = ty; r < 32; r += 8) {
    const float v = t[tx][r];
    const __nv_bfloat16 h = __float2bfloat16(v);
    th[(size_t)(n0 + r) * EE + k0 + tx] = h;
    tl[(size_t)(n0 + r) * EE + k0 + tx] = __float2bfloat16(v - __bfloat162float(h));
  }
}

// ---------------------------------------------------------------------------
// Flash attention (causal), fp32 — unchanged from R1 (passing).
// ---------------------------------------------------------------------------
#define QT_STRIDE 68
#define SMEM_ATTN ((3*64*QT_STRIDE + 64*64) * 4)

__global__ __launch_bounds__(256) void attn_kernel(
    const float* __restrict__ Q, const float* __restrict__ K,
    const float* __restrict__ V, float* __restrict__ O) {
  extern __shared__ float sm[];
  float* Qt = sm;
  float* Kt = Qt + 64*QT_STRIDE;
  float* Ps = Kt + 64*QT_STRIDE;
  float* Vs = Ps + 64*QT_STRIDE;

  const int qt = blockIdx.x, h = blockIdx.y, b = blockIdx.z;
  const int tid = threadIdx.x;
  const int tx = tid & 15, ty = tid >> 4;
  const float scale = 0.125f;
  const size_t base = (size_t)b * TT * EE + (size_t)h * DH;
  const int q0 = qt * 64;

  for (int idx = tid; idx < 64*16; idx += 256) {
    const int r = idx >> 4, c4 = (idx & 15) << 2;
    float4 qv = *(const float4*)&Q[base + (size_t)(q0 + r) * EE + c4];
    Qt[(c4+0)*QT_STRIDE + r] = qv.x;
    Qt[(c4+1)*QT_STRIDE + r] = qv.y;
    Qt[(c4+2)*QT_STRIDE + r] = qv.z;
    Qt[(c4+3)*QT_STRIDE + r] = qv.w;
  }

  float m[4], l[4], o[4][4];
#pragma unroll
  for (int r = 0; r < 4; r++) {
    m[r] = -1e30f; l[r] = 0.f;
#pragma unroll
    for (int c = 0; c < 4; c++) o[r][c] = 0.f;
  }
  __syncthreads();

  for (int kt = 0; kt <= qt; kt++) {
    const int k0 = kt * 64;
    for (int idx = tid; idx < 64*16; idx += 256) {
      const int r = idx >> 4, c4 = (idx & 15) << 2;
      float4 kv = *(const float4*)&K[base + (size_t)(k0 + r) * EE + c4];
      Kt[(c4+0)*QT_STRIDE + r] = kv.x;
      Kt[(c4+1)*QT_STRIDE + r] = kv.y;
      Kt[(c4+2)*QT_STRIDE + r] = kv.z;
      Kt[(c4+3)*QT_STRIDE + r] = kv.w;
      *(float4*)&Vs[r*64 + c4] = *(const float4*)&V[base + (size_t)(k0 + r) * EE + c4];
    }
    __syncthreads();

    float s[4][4];
#pragma unroll
    for (int r = 0; r < 4; r++)
#pragma unroll
      for (int c = 0; c < 4; c++) s[r][c] = 0.f;
#pragma unroll 8
    for (int d = 0; d < 64; d++) {
      float4 qv = *(float4*)&Qt[d*QT_STRIDE + ty*4];
      float4 kv = *(float4*)&Kt[d*QT_STRIDE + tx*4];
      const float qa[4] = {qv.x, qv.y, qv.z, qv.w};
      const float ka[4] = {kv.x, kv.y, kv.z, kv.w};
#pragma unroll
      for (int r = 0; r < 4; r++)
#pragma unroll
        for (int c = 0; c < 4; c++)
          s[r][c] += qa[r] * ka[c];
    }
    const bool diag = (kt == qt);
#pragma unroll
    for (int r = 0; r < 4; r++)
#pragma unroll
      for (int c = 0; c < 4; c++) {
        s[r][c] *= scale;
        if (diag && (tx*4 + c > ty*4 + r)) s[r][c] = -1e30f;
      }

#pragma unroll
    for (int r = 0; r < 4; r++) {
      float tm = fmaxf(fmaxf(s[r][0], s[r][1]), fmaxf(s[r][2], s[r][3]));
#pragma unroll
      for (int off = 8; off; off >>= 1)
        tm = fmaxf(tm, __shfl_xor_sync(0xffffffffu, tm, off));
      const float mn = fmaxf(m[r], tm);
      const float f = __expf(m[r] - mn);
      float rs = 0.f;
#pragma unroll
      for (int c = 0; c < 4; c++) {
        const float p = __expf(s[r][c] - mn);
        s[r][c] = p;
        rs += p;
      }
#pragma unroll
      for (int off = 8; off; off >>= 1)
        rs += __shfl_xor_sync(0xffffffffu, rs, off);
      l[r] = l[r] * f + rs;
      m[r] = mn;
#pragma unroll
      for (int c = 0; c < 4; c++) o[r][c] *= f;
      *(float4*)&Ps[(ty*4 + r)*QT_STRIDE + tx*4] =
          make_float4(s[r][0], s[r][1], s[r][2], s[r][3]);
    }
    __syncthreads();

#pragma unroll 4
    for (int j = 0; j < 64; j++) {
      float4 vv = *(float4*)&Vs[j*64 + tx*4];
      const float va[4] = {vv.x, vv.y, vv.z, vv.w};
      const float p0 = Ps[(ty*4+0)*QT_STRIDE + j];
      const float p1 = Ps[(ty*4+1)*QT_STRIDE + j];
      const float p2 = Ps[(ty*4+2)*QT_STRIDE + j];
      const float p3 = Ps[(ty*4+3)*QT_STRIDE + j];
#pragma unroll
      for (int c = 0; c < 4; c++) {
        o[0][c] += p0 * va[c];
        o[1][c] += p1 * va[c];
        o[2][c] += p2 * va[c];
        o[3][c] += p3 * va[c];
      }
    }
    __syncthreads();
  }

#pragma unroll
  for (int r = 0; r < 4; r++) {
    const float inv = 1.f / l[r];
    float4 w = make_float4(o[r][0]*inv, o[r][1]*inv, o[r][2]*inv, o[r][3]*inv);
    *(float4*)&O[base + (size_t)(q0 + ty*4 + r) * EE + tx*4] = w;
  }
}

// ---------------------------------------------------------------------------
extern "C" void kernel_launch(void* const* d_in, const int* in_sizes, int n_in,
                              void* d_out, int out_size) {
  const float* x  = (const float*)d_in[0];
  const float* Wq = (const float*)d_in[1];
  const float* Wk = (const float*)d_in[2];
  const float* Wv = (const float*)d_in[3];
  const float* Wo = (const float*)d_in[4];
  const float* bo = (const float*)d_in[5];
  float* out = (float*)d_out;

  float *q, *k, *v, *ao;
  __nv_bfloat16 *xh, *xl, *aoh, *aol, *wth, *wtl;
  cudaGetSymbolAddress((void**)&q,   g_q);
  cudaGetSymbolAddress((void**)&k,   g_k);
  cudaGetSymbolAddress((void**)&v,   g_v);
  cudaGetSymbolAddress((void**)&ao,  g_ao);
  cudaGetSymbolAddress((void**)&xh,  g_xh);
  cudaGetSymbolAddress((void**)&xl,  g_xl);
  cudaGetSymbolAddress((void**)&aoh, g_aoh);
  cudaGetSymbolAddress((void**)&aol, g_aol);
  cudaGetSymbolAddress((void**)&wth, g_wth);
  cudaGetSymbolAddress((void**)&wtl, g_wtl);

  cudaFuncSetAttribute(attn_kernel,
                       cudaFuncAttributeMaxDynamicSharedMemorySize, SMEM_ATTN);
  cudaFuncSetAttribute(mm_hmma,
                       cudaFuncAttributeMaxDynamicSharedMemorySize, MM_SMEM);

  // 1) split x; transpose+split weights
  convert_split_kernel<<<(MROWS*EE/4 + 255)/256, 256>>>(
      (const float4*)x, (ushort4*)xh, (ushort4*)xl, MROWS*EE/4);
  dim3 tgrid(EE/32, EE/32);
  transpose_split_kernel<<<tgrid, 256>>>(Wq, wth + 0*(size_t)EE*EE, wtl + 0*(size_t)EE*EE);
  transpose_split_kernel<<<tgrid, 256>>>(Wk, wth + 1*(size_t)EE*EE, wtl + 1*(size_t)EE*EE);
  transpose_split_kernel<<<tgrid, 256>>>(Wv, wth + 2*(size_t)EE*EE, wtl + 2*(size_t)EE*EE);
  transpose_split_kernel<<<tgrid, 256>>>(Wo, wth + 3*(size_t)EE*EE, wtl + 3*(size_t)EE*EE);

  // 2) q/k/v projections on tensor cores (HMMA)
  dim3 ggrid(EE/128, MROWS/128);   // (8, 32)
  mm_hmma<<<ggrid, 256, MM_SMEM>>>(xh, xl, wth + 0*(size_t)EE*EE, wtl + 0*(size_t)EE*EE, q, nullptr);
  mm_hmma<<<ggrid, 256, MM_SMEM>>>(xh, xl, wth + 1*(size_t)EE*EE, wtl + 1*(size_t)EE*EE, k, nullptr);
  mm_hmma<<<ggrid, 256, MM_SMEM>>>(xh, xl, wth + 2*(size_t)EE*EE, wtl + 2*(size_t)EE*EE, v, nullptr);

  // 3) attention (fp32 SIMT, unchanged)
  dim3 agrid(TT/64, HH, BB);       // (32, 16, 2)
  attn_kernel<<<agrid, 256, SMEM_ATTN>>>(q, k, v, ao);

  // 4) output projection
  convert_split_kernel<<<(MROWS*EE/4 + 255)/256, 256>>>(
      (const float4*)ao, (ushort4*)aoh, (ushort4*)aol, MROWS*EE/4);
  mm_hmma<<<ggrid, 256, MM_SMEM>>>(aoh, aol, wth + 3*(size_t)EE*EE, wtl + 3*(size_t)EE*EE, out, bo);
}

// round 4
// speedup vs baseline: 2.3332x; 1.6967x over previous
#include <cuda_runtime.h>
#include <cuda_bf16.h>
#include <math.h>
#include <stdint.h>

#define BB 2
#define TT 2048
#define EE 1024
#define HH 16
#define DH 64
#define MROWS (BB*TT)   /* 4096 */
#define NKEL ((size_t)MROWS*EE)

// ---------------- scratch (__device__ globals; no allocs allowed) ----------
__device__ __align__(1024) __nv_bfloat16 g_xh  [MROWS*EE];
__device__ __align__(1024) __nv_bfloat16 g_xl  [MROWS*EE];
__device__ __align__(1024) __nv_bfloat16 g_qkvh[3*MROWS*EE];  // q,k,v hi
__device__ __align__(1024) __nv_bfloat16 g_qkvl[3*MROWS*EE];  // q,k,v lo
__device__ __align__(1024) __nv_bfloat16 g_aoh [MROWS*EE];
__device__ __align__(1024) __nv_bfloat16 g_aol [MROWS*EE];
__device__ __align__(1024) __nv_bfloat16 g_wth [4*EE*EE];     // W^T hi [4096,1024]
__device__ __align__(1024) __nv_bfloat16 g_wtl [4*EE*EE];     // W^T lo

// ---------------- PTX helpers (baseline ISA only) ---------------------------
__device__ __forceinline__ uint32_t smem_to_u32(const void* p) {
  uint32_t a;
  asm("{ .reg .u64 t; cvta.to.shared.u64 t, %1; cvt.u32.u64 %0, t; }"
      : "=r"(a) : "l"(p));
  return a;
}
__device__ __forceinline__ void cpa16(uint32_t d, const void* s) {
  asm volatile("cp.async.cg.shared.global [%0], [%1], 16;" :: "r"(d), "l"(s) : "memory");
}
#define CP_COMMIT() asm volatile("cp.async.commit_group;" ::: "memory")
#define CP_WAIT(n)  asm volatile("cp.async.wait_group %0;" :: "n"(n) : "memory")

#define HMMA16816(d, a0, a1, a2, a3, b0, b1)                                   \
  asm volatile("mma.sync.aligned.m16n8k16.row.col.f32.bf16.bf16.f32 "          \
    "{%0,%1,%2,%3}, {%4,%5,%6,%7}, {%8,%9}, {%0,%1,%2,%3};"                    \
    : "+f"((d)[0]), "+f"((d)[1]), "+f"((d)[2]), "+f"((d)[3])                   \
    : "r"(a0), "r"(a1), "r"(a2), "r"(a3), "r"(b0), "r"(b1))

#define LDMX4T(r0, r1, r2, r3, addr)                                           \
  asm volatile("ldmatrix.sync.aligned.m8n8.x4.trans.shared.b16 "               \
    "{%0,%1,%2,%3}, [%4];"                                                     \
    : "=r"(r0), "=r"(r1), "=r"(r2), "=r"(r3) : "r"(addr))

// split two fp32 into packed bf16 hi-pair and lo-pair (residual)
__device__ __forceinline__ void split2(float x, float y, uint32_t& hi, uint32_t& lo) {
  __nv_bfloat16 hx = __float2bfloat16(x), hy = __float2bfloat16(y);
  __nv_bfloat162 hh; hh.x = hx; hh.y = hy;
  __nv_bfloat162 ll;
  ll.x = __float2bfloat16(x - __bfloat162float(hx));
  ll.y = __float2bfloat16(y - __bfloat162float(hy));
  hi = *(uint32_t*)&hh; lo = *(uint32_t*)&ll;
}

// ---------------------------------------------------------------------------
// HMMA GEMM: C[4096, N] = A[4096,1024] @ B^T (+ bias), 3-pass split precision.
// If oh != nullptr: N=3072 fused QKV mode, writes bf16 hi/lo to g_qkv{h,l}.
// Else: fp32 out + bias (N=1024).
// ---------------------------------------------------------------------------
#define RS   80
#define MAT  (128*RS)
#define STG  (4*MAT)
#define MM_SMEM (2*STG)
#define KT   (EE/32)

__global__ __launch_bounds__(256) void mm_hmma(
    const __nv_bfloat16* __restrict__ Ah, const __nv_bfloat16* __restrict__ Al,
    const __nv_bfloat16* __restrict__ Bh, const __nv_bfloat16* __restrict__ Bl,
    float* __restrict__ C, const float* __restrict__ bias,
    __nv_bfloat16* __restrict__ oh, __nv_bfloat16* __restrict__ ol) {
  extern __shared__ char smg[];
  const int tid = threadIdx.x, wid = tid >> 5, lane = tid & 31;
  const int g = lane >> 2, tg = lane & 3;
  const int m0 = blockIdx.y * 128, n0 = blockIdx.x * 128;
  const int wm = (wid & 1) * 64, wn = (wid >> 1) * 32;
  const uint32_t sbase = smem_to_u32(smg);

  const int lrow = tid >> 1;
  const int lch  = (tid & 1) * 2;
  const __nv_bfloat16* pAh = Ah + (size_t)(m0 + lrow) * EE + lch * 8;
  const __nv_bfloat16* pAl = Al + (size_t)(m0 + lrow) * EE + lch * 8;
  const __nv_bfloat16* pBh = Bh + (size_t)(n0 + lrow) * EE + lch * 8;
  const __nv_bfloat16* pBl = Bl + (size_t)(n0 + lrow) * EE + lch * 8;
  const uint32_t dbase = sbase + lrow * RS + lch * 16;

  float acc[4][4][4];
#pragma unroll
  for (int i = 0; i < 4; i++)
#pragma unroll
    for (int j = 0; j < 4; j++)
#pragma unroll
      for (int c = 0; c < 4; c++) acc[i][j][c] = 0.f;

  {
    const uint32_t d = dbase;
    cpa16(d,             pAh); cpa16(d + 16,            pAh + 8);
    cpa16(d + MAT,       pAl); cpa16(d + MAT + 16,      pAl + 8);
    cpa16(d + 2*MAT,     pBh); cpa16(d + 2*MAT + 16,    pBh + 8);
    cpa16(d + 3*MAT,     pBl); cpa16(d + 3*MAT + 16,    pBl + 8);
    CP_COMMIT();
  }

  for (int it = 0; it < KT; it++) {
    if (it + 1 < KT) {
      const int k0 = (it + 1) * 32;
      const uint32_t d = dbase + ((it + 1) & 1) * STG;
      cpa16(d,          pAh + k0); cpa16(d + 16,         pAh + k0 + 8);
      cpa16(d + MAT,    pAl + k0); cpa16(d + MAT + 16,   pAl + k0 + 8);
      cpa16(d + 2*MAT,  pBh + k0); cpa16(d + 2*MAT + 16, pBh + k0 + 8);
      cpa16(d + 3*MAT,  pBl + k0); cpa16(d + 3*MAT + 16, pBl + k0 + 8);
      CP_COMMIT();
      CP_WAIT(1);
    } else {
      CP_WAIT(0);
    }
    __syncthreads();

    const char* stb = smg + (it & 1) * STG;
#pragma unroll
    for (int pass = 0; pass < 3; pass++) {
      const char* Abase = stb + (pass == 2 ? MAT : 0);
      const char* Bbase = stb + 2 * MAT + (pass == 1 ? MAT : 0);
#pragma unroll
      for (int ks = 0; ks < 2; ks++) {
        uint32_t b0[4], b1[4];
#pragma unroll
        for (int j = 0; j < 4; j++) {
          const char* bp = Bbase + (wn + j * 8 + g) * RS + ks * 32 + tg * 4;
          b0[j] = *(const uint32_t*)bp;
          b1[j] = *(const uint32_t*)(bp + 16);
        }
#pragma unroll
        for (int i = 0; i < 4; i++) {
          const char* ap = Abase + (wm + i * 16 + g) * RS + ks * 32 + tg * 4;
          const uint32_t a0 = *(const uint32_t*)ap;
          const uint32_t a1 = *(const uint32_t*)(ap + 8 * RS);
          const uint32_t a2 = *(const uint32_t*)(ap + 16);
          const uint32_t a3 = *(const uint32_t*)(ap + 8 * RS + 16);
#pragma unroll
          for (int j = 0; j < 4; j++)
            HMMA16816(acc[i][j], a0, a1, a2, a3, b0[j], b1[j]);
        }
      }
    }
    __syncthreads();
  }

  if (oh) {
    // fused QKV epilogue: split to bf16 hi/lo, scatter to q/k/v sub-arrays
#pragma unroll
    for (int i = 0; i < 4; i++) {
      const int r0 = m0 + wm + i * 16 + g;
#pragma unroll
      for (int j = 0; j < 4; j++) {
        const int cg = n0 + wn + j * 8 + tg * 2;
        const int which = cg >> 10, ncol = cg & 1023;
        const size_t e0 = (size_t)which * NKEL + (size_t)r0 * EE + ncol;
        const size_t e1 = e0 + 8 * EE;
        uint32_t h0, l0, h1, l1;
        split2(acc[i][j][0], acc[i][j][1], h0, l0);
        split2(acc[i][j][2], acc[i][j][3], h1, l1);
        *(uint32_t*)(oh + e0) = h0; *(uint32_t*)(ol + e0) = l0;
        *(uint32_t*)(oh + e1) = h1; *(uint32_t*)(ol + e1) = l1;
      }
    }
  } else {
#pragma unroll
    for (int i = 0; i < 4; i++) {
      const int r0 = m0 + wm + i * 16 + g;
#pragma unroll
      for (int j = 0; j < 4; j++) {
        const int c = n0 + wn + j * 8 + tg * 2;
        float bx = 0.f, by = 0.f;
        if (bias) { bx = bias[c]; by = bias[c + 1]; }
        float2 v0 = make_float2(acc[i][j][0] + bx, acc[i][j][1] + by);
        float2 v1 = make_float2(acc[i][j][2] + bx, acc[i][j][3] + by);
        *(float2*)&C[(size_t)r0 * EE + c]       = v0;
        *(float2*)&C[(size_t)(r0 + 8) * EE + c] = v1;
      }
    }
  }
}

// ---------------------------------------------------------------------------
// HMMA flash attention (causal), split precision everywhere.
// CTA: 128 q-rows x (h, b). 8 warps, 16 q-rows each. k-tiles of 64 keys.
// ---------------------------------------------------------------------------
#define SKB 9216              /* 64 rows x 144 B */
#define ATT_SMEM (4*SKB)      /* Kh, Kl, Vh, Vl */

__global__ __launch_bounds__(256, 2) void attn_hmma(
    const __nv_bfloat16* __restrict__ qkvh,
    const __nv_bfloat16* __restrict__ qkvl,
    __nv_bfloat16* __restrict__ aoh, __nv_bfloat16* __restrict__ aol) {
  extern __shared__ char sma[];
  const uint32_t sb = smem_to_u32(sma);
  const int tid = threadIdx.x, wid = tid >> 5, lane = tid & 31;
  const int g = lane >> 2, tg = lane & 3;
  const int qt = (int)gridDim.x - 1 - (int)blockIdx.x;   // heavy tiles first
  const int h = blockIdx.y, b = blockIdx.z;
  const int q0 = qt * 128;
  const int grow = q0 + wid * 16 + g;       // row of frag regs {0,1}; +8 for {2,3}
  const float scale = 0.125f;

  // ---- Q a-frags (hi/lo) straight from gmem, kept in regs
  const __nv_bfloat16* qph = qkvh + (size_t)(b * TT + grow) * EE + h * DH;
  const __nv_bfloat16* qpl = qkvl + (size_t)(b * TT + grow) * EE + h * DH;
  uint32_t qa[2][4][4];
#pragma unroll
  for (int ks = 0; ks < 4; ks++) {
    qa[0][ks][0] = *(const uint32_t*)(qph + ks * 16 + 2 * tg);
    qa[0][ks][1] = *(const uint32_t*)(qph + 8 * EE + ks * 16 + 2 * tg);
    qa[0][ks][2] = *(const uint32_t*)(qph + ks * 16 + 8 + 2 * tg);
    qa[0][ks][3] = *(const uint32_t*)(qph + 8 * EE + ks * 16 + 8 + 2 * tg);
    qa[1][ks][0] = *(const uint32_t*)(qpl + ks * 16 + 2 * tg);
    qa[1][ks][1] = *(const uint32_t*)(qpl + 8 * EE + ks * 16 + 2 * tg);
    qa[1][ks][2] = *(const uint32_t*)(qpl + ks * 16 + 8 + 2 * tg);
    qa[1][ks][3] = *(const uint32_t*)(qpl + 8 * EE + ks * 16 + 8 + 2 * tg);
  }

  float O[8][4];
#pragma unroll
  for (int nt = 0; nt < 8; nt++)
#pragma unroll
    for (int c = 0; c < 4; c++) O[nt][c] = 0.f;
  float mx0 = -1e30f, mx1 = -1e30f, lr0 = 0.f, lr1 = 0.f;

  // cp.async mapping: 64 rows x 8 chunks per matrix; 256 threads -> 2 rows each
  const int lc = tid & 7, lrr = tid >> 3;   // lrr 0..31
  const uint32_t dK = lrr * 144 + lc * 16;
  const size_t kvoff = (size_t)(b * TT) * EE + h * DH + lc * 8;
  const __nv_bfloat16* Ksh = qkvh + NKEL     + kvoff;
  const __nv_bfloat16* Ksl = qkvl + NKEL     + kvoff;
  const __nv_bfloat16* Vsh = qkvh + 2 * NKEL + kvoff;
  const __nv_bfloat16* Vsl = qkvl + 2 * NKEL + kvoff;

  // ldmatrix per-lane base (within a 64x64 tile): matrix id = lane>>3
  const int lmat = lane >> 3, lrow8 = lane & 7;
  const int lm_key = (lmat & 1) * 8 + lrow8;
  const int lm_dh  = (lmat >> 1) * 8;
  const uint32_t vbase = sb + 2 * SKB + lm_key * 144 + lm_dh * 2;

  const int ktmax = 2 * qt + 1;
  for (int kt = 0; kt <= ktmax; kt++) {
    const int kk0 = kt * 64;
    {
      const size_t ro = (size_t)(kk0 + lrr) * EE;
      cpa16(sb + dK,           Ksh + ro); cpa16(sb + dK + 32 * 144,           Ksh + ro + (size_t)32 * EE);
      cpa16(sb + SKB + dK,     Ksl + ro); cpa16(sb + SKB + dK + 32 * 144,     Ksl + ro + (size_t)32 * EE);
      cpa16(sb + 2*SKB + dK,   Vsh + ro); cpa16(sb + 2*SKB + dK + 32 * 144,   Vsh + ro + (size_t)32 * EE);
      cpa16(sb + 3*SKB + dK,   Vsl + ro); cpa16(sb + 3*SKB + dK + 32 * 144,   Vsl + ro + (size_t)32 * EE);
      CP_COMMIT(); CP_WAIT(0);
    }
    __syncthreads();

    // ---- S = Q K^T (3-pass split)
    float sacc[8][4];
#pragma unroll
    for (int j = 0; j < 8; j++)
#pragma unroll
      for (int c = 0; c < 4; c++) sacc[j][c] = 0.f;
#pragma unroll
    for (int ks = 0; ks < 4; ks++) {
#pragma unroll
      for (int j = 0; j < 8; j++) {
        const char* pk = sma + (j * 8 + g) * 144 + (ks * 16 + 2 * tg) * 2;
        const uint32_t bh0 = *(const uint32_t*)pk;
        const uint32_t bh1 = *(const uint32_t*)(pk + 16);
        const uint32_t bl0 = *(const uint32_t*)(pk + SKB);
        const uint32_t bl1 = *(const uint32_t*)(pk + SKB + 16);
        HMMA16816(sacc[j], qa[0][ks][0], qa[0][ks][1], qa[0][ks][2], qa[0][ks][3], bh0, bh1);
        HMMA16816(sacc[j], qa[0][ks][0], qa[0][ks][1], qa[0][ks][2], qa[0][ks][3], bl0, bl1);
        HMMA16816(sacc[j], qa[1][ks][0], qa[1][ks][1], qa[1][ks][2], qa[1][ks][3], bh0, bh1);
      }
    }

    // ---- scale + causal mask
    const bool needmask = (kk0 + 63 > q0 + wid * 16);
#pragma unroll
    for (int j = 0; j < 8; j++) {
#pragma unroll
      for (int c = 0; c < 4; c++) sacc[j][c] *= scale;
      if (needmask) {
        const int col = kk0 + j * 8 + 2 * tg;
        if (col     > grow)     sacc[j][0] = -1e30f;
        if (col + 1 > grow)     sacc[j][1] = -1e30f;
        if (col     > grow + 8) sacc[j][2] = -1e30f;
        if (col + 1 > grow + 8) sacc[j][3] = -1e30f;
      }
    }

    // ---- online softmax (rows grow, grow+8)
    float mr0 = -1e30f, mr1 = -1e30f;
#pragma unroll
    for (int j = 0; j < 8; j++) {
      mr0 = fmaxf(mr0, fmaxf(sacc[j][0], sacc[j][1]));
      mr1 = fmaxf(mr1, fmaxf(sacc[j][2], sacc[j][3]));
    }
#pragma unroll
    for (int off = 1; off <= 2; off <<= 1) {
      mr0 = fmaxf(mr0, __shfl_xor_sync(0xffffffffu, mr0, off));
      mr1 = fmaxf(mr1, __shfl_xor_sync(0xffffffffu, mr1, off));
    }
    const float mn0 = fmaxf(mx0, mr0), mn1 = fmaxf(mx1, mr1);
    const float f0 = __expf(mx0 - mn0), f1 = __expf(mx1 - mn1);
    float rs0 = 0.f, rs1 = 0.f;
#pragma unroll
    for (int j = 0; j < 8; j++) {
      sacc[j][0] = __expf(sacc[j][0] - mn0);
      sacc[j][1] = __expf(sacc[j][1] - mn0);
      sacc[j][2] = __expf(sacc[j][2] - mn1);
      sacc[j][3] = __expf(sacc[j][3] - mn1);
      rs0 += sacc[j][0] + sacc[j][1];
      rs1 += sacc[j][2] + sacc[j][3];
    }
#pragma unroll
    for (int off = 1; off <= 2; off <<= 1) {
      rs0 += __shfl_xor_sync(0xffffffffu, rs0, off);
      rs1 += __shfl_xor_sync(0xffffffffu, rs1, off);
    }
    lr0 = lr0 * f0 + rs0; mx0 = mn0;
    lr1 = lr1 * f1 + rs1; mx1 = mn1;
#pragma unroll
    for (int nt = 0; nt < 8; nt++) {
      O[nt][0] *= f0; O[nt][1] *= f0; O[nt][2] *= f1; O[nt][3] *= f1;
    }

    // ---- O += P V (3-pass split; P frags from S regs, V via ldmatrix.trans)
#pragma unroll
    for (int kc = 0; kc < 4; kc++) {
      uint32_t ah[4], al[4];
      split2(sacc[2*kc][0],   sacc[2*kc][1],   ah[0], al[0]);
      split2(sacc[2*kc][2],   sacc[2*kc][3],   ah[1], al[1]);
      split2(sacc[2*kc+1][0], sacc[2*kc+1][1], ah[2], al[2]);
      split2(sacc[2*kc+1][2], sacc[2*kc+1][3], ah[3], al[3]);
      const uint32_t vrow = vbase + kc * 16 * 144;
#pragma unroll
      for (int np = 0; np < 4; np++) {
        uint32_t vh0, vh1, vh2, vh3, vl0, vl1, vl2, vl3;
        LDMX4T(vh0, vh1, vh2, vh3, vrow + np * 32);
        LDMX4T(vl0, vl1, vl2, vl3, vrow + np * 32 + SKB);
        HMMA16816(O[2*np],   ah[0], ah[1], ah[2], ah[3], vh0, vh1);
        HMMA16816(O[2*np],   ah[0], ah[1], ah[2], ah[3], vl0, vl1);
        HMMA16816(O[2*np],   al[0], al[1], al[2], al[3], vh0, vh1);
        HMMA16816(O[2*np+1], ah[0], ah[1], ah[2], ah[3], vh2, vh3);
        HMMA16816(O[2*np+1], ah[0], ah[1], ah[2], ah[3], vl2, vl3);
        HMMA16816(O[2*np+1], al[0], al[1], al[2], al[3], vh2, vh3);
      }
    }
    __syncthreads();
  }

  // ---- epilogue: normalize, split to hi/lo bf16, store
  const float inv0 = 1.f / lr0, inv1 = 1.f / lr1;
  const size_t o0 = (size_t)(b * TT + grow) * EE + h * DH + 2 * tg;
#pragma unroll
  for (int nt = 0; nt < 8; nt++) {
    uint32_t h0, l0, h1, l1;
    split2(O[nt][0] * inv0, O[nt][1] * inv0, h0, l0);
    split2(O[nt][2] * inv1, O[nt][3] * inv1, h1, l1);
    *(uint32_t*)(aoh + o0 + nt * 8)          = h0;
    *(uint32_t*)(aol + o0 + nt * 8)          = l0;
    *(uint32_t*)(aoh + o0 + 8 * EE + nt * 8) = h1;
    *(uint32_t*)(aol + o0 + 8 * EE + nt * 8) = l1;
  }
}

// ---------------------------------------------------------------------------
// fp32 -> bf16 hi/lo split (x input)
// ---------------------------------------------------------------------------
__global__ __launch_bounds__(256) void convert_split_kernel(
    const float4* __restrict__ in, ushort4* __restrict__ hi,
    ushort4* __restrict__ lo, int n4) {
  const int i = blockIdx.x * 256 + threadIdx.x;
  if (i >= n4) return;
  const float4 v = in[i];
  ushort4 h, l;
  __nv_bfloat16 t;
  t = __float2bfloat16(v.x); h.x = __bfloat16_as_ushort(t);
  l.x = __bfloat16_as_ushort(__float2bfloat16(v.x - __bfloat162float(t)));
  t = __float2bfloat16(v.y); h.y = __bfloat16_as_ushort(t);
  l.y = __bfloat16_as_ushort(__float2bfloat16(v.y - __bfloat162float(t)));
  t = __float2bfloat16(v.z); h.z = __bfloat16_as_ushort(t);
  l.z = __bfloat16_as_ushort(__float2bfloat16(v.z - __bfloat162float(t)));
  t = __float2bfloat16(v.w); h.w = __bfloat16_as_ushort(t);
  l.w = __bfloat16_as_ushort(__float2bfloat16(v.w - __bfloat162float(t)));
  hi[i] = h; lo[i] = l;
}

// ---------------------------------------------------------------------------
// W[K,N] fp32 -> W^T hi/lo [N,K] bf16
// ---------------------------------------------------------------------------
__global__ __launch_bounds__(256) void transpose_split_kernel(
    const float* __restrict__ W, __nv_bfloat16* __restrict__ th,
    __nv_bfloat16* __restrict__ tl) {
  __shared__ float t[32][33];
  const int n0 = blockIdx.x * 32, k0 = blockIdx.y * 32;
  const int tx = threadIdx.x & 31, ty = threadIdx.x >> 5;
  for (int r = ty; r < 32; r += 8)
    t[r][tx] = W[(size_t)(k0 + r) * EE + n0 + tx];
  __syncthreads();
  for (int r = ty; r < 32; r += 8) {
    const float v = t[tx][r];
    const __nv_bfloat16 hh = __float2bfloat16(v);
    th[(size_t)(n0 + r) * EE + k0 + tx] = hh;
    tl[(size_t)(n0 + r) * EE + k0 + tx] = __float2bfloat16(v - __bfloat162float(hh));
  }
}

// ---------------------------------------------------------------------------
extern "C" void kernel_launch(void* const* d_in, const int* in_sizes, int n_in,
                              void* d_out, int out_size) {
  const float* x  = (const float*)d_in[0];
  const float* Wq = (const float*)d_in[1];
  const float* Wk = (const float*)d_in[2];
  const float* Wv = (const float*)d_in[3];
  const float* Wo = (const float*)d_in[4];
  const float* bo = (const float*)d_in[5];
  float* out = (float*)d_out;

  __nv_bfloat16 *xh, *xl, *qkvh, *qkvl, *aoh, *aol, *wth, *wtl;
  cudaGetSymbolAddress((void**)&xh,   g_xh);
  cudaGetSymbolAddress((void**)&xl,   g_xl);
  cudaGetSymbolAddress((void**)&qkvh, g_qkvh);
  cudaGetSymbolAddress((void**)&qkvl, g_qkvl);
  cudaGetSymbolAddress((void**)&aoh,  g_aoh);
  cudaGetSymbolAddress((void**)&aol,  g_aol);
  cudaGetSymbolAddress((void**)&wth,  g_wth);
  cudaGetSymbolAddress((void**)&wtl,  g_wtl);

  cudaFuncSetAttribute(mm_hmma,
                       cudaFuncAttributeMaxDynamicSharedMemorySize, MM_SMEM);
  cudaFuncSetAttribute(attn_hmma,
                       cudaFuncAttributeMaxDynamicSharedMemorySize, ATT_SMEM);

  // 1) split x; transpose+split weights (Wq,Wk,Wv consecutive => fused [3072,1024])
  convert_split_kernel<<<(MROWS*EE/4 + 255)/256, 256>>>(
      (const float4*)x, (ushort4*)xh, (ushort4*)xl, MROWS*EE/4);
  dim3 tgrid(EE/32, EE/32);
  transpose_split_kernel<<<tgrid, 256>>>(Wq, wth + 0*(size_t)EE*EE, wtl + 0*(size_t)EE*EE);
  transpose_split_kernel<<<tgrid, 256>>>(Wk, wth + 1*(size_t)EE*EE, wtl + 1*(size_t)EE*EE);
  transpose_split_kernel<<<tgrid, 256>>>(Wv, wth + 2*(size_t)EE*EE, wtl + 2*(size_t)EE*EE);
  transpose_split_kernel<<<tgrid, 256>>>(Wo, wth + 3*(size_t)EE*EE, wtl + 3*(size_t)EE*EE);

  // 2) fused QKV projection (N=3072), epilogue writes bf16 hi/lo
  dim3 qgrid(3*EE/128, MROWS/128);   // (24, 32)
  mm_hmma<<<qgrid, 256, MM_SMEM>>>(xh, xl, wth, wtl, nullptr, nullptr, qkvh, qkvl);

  // 3) HMMA flash attention -> aoh/aol
  dim3 agrid(TT/128, HH, BB);        // (16, 16, 2)
  attn_hmma<<<agrid, 256, ATT_SMEM>>>(qkvh, qkvl, aoh, aol);

  // 4) output projection (fp32 + bias)
  dim3 ogrid(EE/128, MROWS/128);     // (8, 32)
  mm_hmma<<<ogrid, 256, MM_SMEM>>>(aoh, aol, wth + 3*(size_t)EE*EE, wtl + 3*(size_t)EE*EE,
                                   out, bo, nullptr, nullptr);
}

// round 5
// speedup vs baseline: 2.3577x; 1.0105x over previous
#include <cuda_runtime.h>
#include <cuda_bf16.h>
#include <math.h>
#include <stdint.h>

#define BB 2
#define TT 2048
#define EE 1024
#define HH 16
#define DH 64
#define MROWS (BB*TT)   /* 4096 */
#define NKEL ((size_t)MROWS*EE)

// ---------------- scratch (__device__ globals; no allocs allowed) ----------
__device__ __align__(1024) __nv_bfloat16 g_xh  [MROWS*EE];
__device__ __align__(1024) __nv_bfloat16 g_xl  [MROWS*EE];
__device__ __align__(1024) __nv_bfloat16 g_qkvh[3*MROWS*EE];  // q,k,v hi
__device__ __align__(1024) __nv_bfloat16 g_qkvl[3*MROWS*EE];  // q,k,v lo
__device__ __align__(1024) __nv_bfloat16 g_aoh [MROWS*EE];
__device__ __align__(1024) __nv_bfloat16 g_aol [MROWS*EE];
__device__ __align__(1024) __nv_bfloat16 g_wth [4*EE*EE];     // W^T hi [4096,1024]
__device__ __align__(1024) __nv_bfloat16 g_wtl [4*EE*EE];     // W^T lo

// ---------------- PTX helpers (baseline ISA only) ---------------------------
__device__ __forceinline__ uint32_t smem_to_u32(const void* p) {
  uint32_t a;
  asm("{ .reg .u64 t; cvta.to.shared.u64 t, %1; cvt.u32.u64 %0, t; }"
      : "=r"(a) : "l"(p));
  return a;
}
__device__ __forceinline__ void cpa16(uint32_t d, const void* s) {
  asm volatile("cp.async.cg.shared.global [%0], [%1], 16;" :: "r"(d), "l"(s) : "memory");
}
#define CP_COMMIT() asm volatile("cp.async.commit_group;" ::: "memory")
#define CP_WAIT(n)  asm volatile("cp.async.wait_group %0;" :: "n"(n) : "memory")

#define HMMA16816(d, a0, a1, a2, a3, b0, b1)                                   \
  asm volatile("mma.sync.aligned.m16n8k16.row.col.f32.bf16.bf16.f32 "          \
    "{%0,%1,%2,%3}, {%4,%5,%6,%7}, {%8,%9}, {%0,%1,%2,%3};"                    \
    : "+f"((d)[0]), "+f"((d)[1]), "+f"((d)[2]), "+f"((d)[3])                   \
    : "r"(a0), "r"(a1), "r"(a2), "r"(a3), "r"(b0), "r"(b1))

#define LDMX4T(r0, r1, r2, r3, addr)                                           \
  asm volatile("ldmatrix.sync.aligned.m8n8.x4.trans.shared.b16 "               \
    "{%0,%1,%2,%3}, [%4];"                                                     \
    : "=r"(r0), "=r"(r1), "=r"(r2), "=r"(r3) : "r"(addr))

// split two fp32 into packed bf16 hi-pair and lo-pair (residual)
__device__ __forceinline__ void split2(float x, float y, uint32_t& hi, uint32_t& lo) {
  __nv_bfloat16 hx = __float2bfloat16(x), hy = __float2bfloat16(y);
  __nv_bfloat162 hh; hh.x = hx; hh.y = hy;
  __nv_bfloat162 ll;
  ll.x = __float2bfloat16(x - __bfloat162float(hx));
  ll.y = __float2bfloat16(y - __bfloat162float(hy));
  hi = *(uint32_t*)&hh; lo = *(uint32_t*)&ll;
}

// ---------------------------------------------------------------------------
// HMMA GEMM: C[4096, N] = A[4096,1024] @ B^T (+ bias), 3-pass split precision.
// If oh != nullptr: fused QKV mode, writes bf16 hi/lo split into g_qkv{h,l}.
// ---------------------------------------------------------------------------
#define RS   80
#define MAT  (128*RS)
#define STG  (4*MAT)
#define MM_SMEM (2*STG)
#define KT   (EE/32)

__global__ __launch_bounds__(256) void mm_hmma(
    const __nv_bfloat16* __restrict__ Ah, const __nv_bfloat16* __restrict__ Al,
    const __nv_bfloat16* __restrict__ Bh, const __nv_bfloat16* __restrict__ Bl,
    float* __restrict__ C, const float* __restrict__ bias,
    __nv_bfloat16* __restrict__ oh, __nv_bfloat16* __restrict__ ol) {
  extern __shared__ char smg[];
  const int tid = threadIdx.x, wid = tid >> 5, lane = tid & 31;
  const int g = lane >> 2, tg = lane & 3;
  const int m0 = blockIdx.y * 128, n0 = blockIdx.x * 128;
  const int wm = (wid & 1) * 64, wn = (wid >> 1) * 32;
  const uint32_t sbase = smem_to_u32(smg);

  const int lrow = tid >> 1;
  const int lch  = (tid & 1) * 2;
  const __nv_bfloat16* pAh = Ah + (size_t)(m0 + lrow) * EE + lch * 8;
  const __nv_bfloat16* pAl = Al + (size_t)(m0 + lrow) * EE + lch * 8;
  const __nv_bfloat16* pBh = Bh + (size_t)(n0 + lrow) * EE + lch * 8;
  const __nv_bfloat16* pBl = Bl + (size_t)(n0 + lrow) * EE + lch * 8;
  const uint32_t dbase = sbase + lrow * RS + lch * 16;

  float acc[4][4][4];
#pragma unroll
  for (int i = 0; i < 4; i++)
#pragma unroll
    for (int j = 0; j < 4; j++)
#pragma unroll
      for (int c = 0; c < 4; c++) acc[i][j][c] = 0.f;

  {
    const uint32_t d = dbase;
    cpa16(d,             pAh); cpa16(d + 16,            pAh + 8);
    cpa16(d + MAT,       pAl); cpa16(d + MAT + 16,      pAl + 8);
    cpa16(d + 2*MAT,     pBh); cpa16(d + 2*MAT + 16,    pBh + 8);
    cpa16(d + 3*MAT,     pBl); cpa16(d + 3*MAT + 16,    pBl + 8);
    CP_COMMIT();
  }

  for (int it = 0; it < KT; it++) {
    if (it + 1 < KT) {
      const int k0 = (it + 1) * 32;
      const uint32_t d = dbase + ((it + 1) & 1) * STG;
      cpa16(d,          pAh + k0); cpa16(d + 16,         pAh + k0 + 8);
      cpa16(d + MAT,    pAl + k0); cpa16(d + MAT + 16,   pAl + k0 + 8);
      cpa16(d + 2*MAT,  pBh + k0); cpa16(d + 2*MAT + 16, pBh + k0 + 8);
      cpa16(d + 3*MAT,  pBl + k0); cpa16(d + 3*MAT + 16, pBl + k0 + 8);
      CP_COMMIT();
      CP_WAIT(1);
    } else {
      CP_WAIT(0);
    }
    __syncthreads();

    const char* stb = smg + (it & 1) * STG;
#pragma unroll
    for (int pass = 0; pass < 3; pass++) {
      const char* Abase = stb + (pass == 2 ? MAT : 0);
      const char* Bbase = stb + 2 * MAT + (pass == 1 ? MAT : 0);
#pragma unroll
      for (int ks = 0; ks < 2; ks++) {
        uint32_t b0[4], b1[4];
#pragma unroll
        for (int j = 0; j < 4; j++) {
          const char* bp = Bbase + (wn + j * 8 + g) * RS + ks * 32 + tg * 4;
          b0[j] = *(const uint32_t*)bp;
          b1[j] = *(const uint32_t*)(bp + 16);
        }
#pragma unroll
        for (int i = 0; i < 4; i++) {
          const char* ap = Abase + (wm + i * 16 + g) * RS + ks * 32 + tg * 4;
          const uint32_t a0 = *(const uint32_t*)ap;
          const uint32_t a1 = *(const uint32_t*)(ap + 8 * RS);
          const uint32_t a2 = *(const uint32_t*)(ap + 16);
          const uint32_t a3 = *(const uint32_t*)(ap + 8 * RS + 16);
#pragma unroll
          for (int j = 0; j < 4; j++)
            HMMA16816(acc[i][j], a0, a1, a2, a3, b0[j], b1[j]);
        }
      }
    }
    __syncthreads();
  }

  if (oh) {
#pragma unroll
    for (int i = 0; i < 4; i++) {
      const int r0 = m0 + wm + i * 16 + g;
#pragma unroll
      for (int j = 0; j < 4; j++) {
        const int cg = n0 + wn + j * 8 + tg * 2;
        const int which = cg >> 10, ncol = cg & 1023;
        const size_t e0 = (size_t)which * NKEL + (size_t)r0 * EE + ncol;
        const size_t e1 = e0 + 8 * EE;
        uint32_t h0, l0, h1, l1;
        split2(acc[i][j][0], acc[i][j][1], h0, l0);
        split2(acc[i][j][2], acc[i][j][3], h1, l1);
        *(uint32_t*)(oh + e0) = h0; *(uint32_t*)(ol + e0) = l0;
        *(uint32_t*)(oh + e1) = h1; *(uint32_t*)(ol + e1) = l1;
      }
    }
  } else {
#pragma unroll
    for (int i = 0; i < 4; i++) {
      const int r0 = m0 + wm + i * 16 + g;
#pragma unroll
      for (int j = 0; j < 4; j++) {
        const int c = n0 + wn + j * 8 + tg * 2;
        float bx = 0.f, by = 0.f;
        if (bias) { bx = bias[c]; by = bias[c + 1]; }
        float2 v0 = make_float2(acc[i][j][0] + bx, acc[i][j][1] + by);
        float2 v1 = make_float2(acc[i][j][2] + bx, acc[i][j][3] + by);
        *(float2*)&C[(size_t)r0 * EE + c]       = v0;
        *(float2*)&C[(size_t)(r0 + 8) * EE + c] = v1;
      }
    }
  }
}

// ---------------------------------------------------------------------------
// HMMA flash attention (causal), split precision, DOUBLE-BUFFERED K/V.
// CTA: 128 q-rows x (h, b). 8 warps, 16 q-rows each. k-tiles of 64 keys.
// ---------------------------------------------------------------------------
#define SKB 9216               /* 64 rows x 144 B */
#define ATT_STG (4*SKB)        /* Kh, Kl, Vh, Vl = 36864 */
#define ATT_SMEM (2*ATT_STG)   /* 73728 */

__global__ __launch_bounds__(256, 2) void attn_hmma(
    const __nv_bfloat16* __restrict__ qkvh,
    const __nv_bfloat16* __restrict__ qkvl,
    __nv_bfloat16* __restrict__ aoh, __nv_bfloat16* __restrict__ aol) {
  extern __shared__ char sma[];
  const uint32_t sb = smem_to_u32(sma);
  const int tid = threadIdx.x, wid = tid >> 5, lane = tid & 31;
  const int g = lane >> 2, tg = lane & 3;
  const int qt = (int)gridDim.x - 1 - (int)blockIdx.x;   // heavy tiles first
  const int h = blockIdx.y, b = blockIdx.z;
  const int q0 = qt * 128;
  const int grow = q0 + wid * 16 + g;
  const float scale = 0.125f;

  // ---- Q a-frags (hi/lo) straight from gmem, kept in regs
  const __nv_bfloat16* qph = qkvh + (size_t)(b * TT + grow) * EE + h * DH;
  const __nv_bfloat16* qpl = qkvl + (size_t)(b * TT + grow) * EE + h * DH;
  uint32_t qa[2][4][4];
#pragma unroll
  for (int ks = 0; ks < 4; ks++) {
    qa[0][ks][0] = *(const uint32_t*)(qph + ks * 16 + 2 * tg);
    qa[0][ks][1] = *(const uint32_t*)(qph + 8 * EE + ks * 16 + 2 * tg);
    qa[0][ks][2] = *(const uint32_t*)(qph + ks * 16 + 8 + 2 * tg);
    qa[0][ks][3] = *(const uint32_t*)(qph + 8 * EE + ks * 16 + 8 + 2 * tg);
    qa[1][ks][0] = *(const uint32_t*)(qpl + ks * 16 + 2 * tg);
    qa[1][ks][1] = *(const uint32_t*)(qpl + 8 * EE + ks * 16 + 2 * tg);
    qa[1][ks][2] = *(const uint32_t*)(qpl + ks * 16 + 8 + 2 * tg);
    qa[1][ks][3] = *(const uint32_t*)(qpl + 8 * EE + ks * 16 + 8 + 2 * tg);
  }

  float O[8][4];
#pragma unroll
  for (int nt = 0; nt < 8; nt++)
#pragma unroll
    for (int c = 0; c < 4; c++) O[nt][c] = 0.f;
  float mx0 = -1e30f, mx1 = -1e30f, lr0 = 0.f, lr1 = 0.f;

  // cp.async mapping: 64 rows x 8 chunks per matrix; 256 threads -> 2 rows each
  const int lc = tid & 7, lrr = tid >> 3;
  const uint32_t dK = lrr * 144 + lc * 16;
  const size_t kvoff = (size_t)(b * TT) * EE + h * DH + lc * 8;
  const __nv_bfloat16* Ksh = qkvh + NKEL     + kvoff;
  const __nv_bfloat16* Ksl = qkvl + NKEL     + kvoff;
  const __nv_bfloat16* Vsh = qkvh + 2 * NKEL + kvoff;
  const __nv_bfloat16* Vsl = qkvl + 2 * NKEL + kvoff;

  // ldmatrix per-lane base (within a 64x64 tile)
  const int lmat = lane >> 3, lrow8 = lane & 7;
  const int lm_key = (lmat & 1) * 8 + lrow8;
  const int lm_dh  = (lmat >> 1) * 8;
  const uint32_t vbase = sb + 2 * SKB + lm_key * 144 + lm_dh * 2;

  const int ktmax = 2 * qt + 1;

  // prologue: tile 0 into stage 0
  {
    const size_t ro = (size_t)lrr * EE;
    const uint32_t bs = sb;
    cpa16(bs + dK,         Ksh + ro); cpa16(bs + dK + 32*144,         Ksh + ro + (size_t)32*EE);
    cpa16(bs + SKB + dK,   Ksl + ro); cpa16(bs + SKB + dK + 32*144,   Ksl + ro + (size_t)32*EE);
    cpa16(bs + 2*SKB + dK, Vsh + ro); cpa16(bs + 2*SKB + dK + 32*144, Vsh + ro + (size_t)32*EE);
    cpa16(bs + 3*SKB + dK, Vsl + ro); cpa16(bs + 3*SKB + dK + 32*144, Vsl + ro + (size_t)32*EE);
    CP_COMMIT();
  }

  for (int kt = 0; kt <= ktmax; kt++) {
    const int st = kt & 1;
    const uint32_t soff = st * ATT_STG;
    if (kt + 1 <= ktmax) {
      const size_t ro = (size_t)((kt + 1) * 64 + lrr) * EE;
      const uint32_t bs = sb + (soff ^ ATT_STG);
      cpa16(bs + dK,         Ksh + ro); cpa16(bs + dK + 32*144,         Ksh + ro + (size_t)32*EE);
      cpa16(bs + SKB + dK,   Ksl + ro); cpa16(bs + SKB + dK + 32*144,   Ksl + ro + (size_t)32*EE);
      cpa16(bs + 2*SKB + dK, Vsh + ro); cpa16(bs + 2*SKB + dK + 32*144, Vsh + ro + (size_t)32*EE);
      cpa16(bs + 3*SKB + dK, Vsl + ro); cpa16(bs + 3*SKB + dK + 32*144, Vsl + ro + (size_t)32*EE);
      CP_COMMIT();
      CP_WAIT(1);
    } else {
      CP_WAIT(0);
    }
    __syncthreads();

    const char* stp = sma + soff;
    const int kk0 = kt * 64;

    // ---- S = Q K^T (3-pass split)
    float sacc[8][4];
#pragma unroll
    for (int j = 0; j < 8; j++)
#pragma unroll
      for (int c = 0; c < 4; c++) sacc[j][c] = 0.f;
#pragma unroll
    for (int ks = 0; ks < 4; ks++) {
#pragma unroll
      for (int j = 0; j < 8; j++) {
        const char* pk = stp + (j * 8 + g) * 144 + (ks * 16 + 2 * tg) * 2;
        const uint32_t bh0 = *(const uint32_t*)pk;
        const uint32_t bh1 = *(const uint32_t*)(pk + 16);
        const uint32_t bl0 = *(const uint32_t*)(pk + SKB);
        const uint32_t bl1 = *(const uint32_t*)(pk + SKB + 16);
        HMMA16816(sacc[j], qa[0][ks][0], qa[0][ks][1], qa[0][ks][2], qa[0][ks][3], bh0, bh1);
        HMMA16816(sacc[j], qa[0][ks][0], qa[0][ks][1], qa[0][ks][2], qa[0][ks][3], bl0, bl1);
        HMMA16816(sacc[j], qa[1][ks][0], qa[1][ks][1], qa[1][ks][2], qa[1][ks][3], bh0, bh1);
      }
    }

    // ---- scale + causal mask
    const bool needmask = (kk0 + 63 > q0 + wid * 16);
#pragma unroll
    for (int j = 0; j < 8; j++) {
#pragma unroll
      for (int c = 0; c < 4; c++) sacc[j][c] *= scale;
      if (needmask) {
        const int col = kk0 + j * 8 + 2 * tg;
        if (col     > grow)     sacc[j][0] = -1e30f;
        if (col + 1 > grow)     sacc[j][1] = -1e30f;
        if (col     > grow + 8) sacc[j][2] = -1e30f;
        if (col + 1 > grow + 8) sacc[j][3] = -1e30f;
      }
    }

    // ---- online softmax
    float mr0 = -1e30f, mr1 = -1e30f;
#pragma unroll
    for (int j = 0; j < 8; j++) {
      mr0 = fmaxf(mr0, fmaxf(sacc[j][0], sacc[j][1]));
      mr1 = fmaxf(mr1, fmaxf(sacc[j][2], sacc[j][3]));
    }
#pragma unroll
    for (int off = 1; off <= 2; off <<= 1) {
      mr0 = fmaxf(mr0, __shfl_xor_sync(0xffffffffu, mr0, off));
      mr1 = fmaxf(mr1, __shfl_xor_sync(0xffffffffu, mr1, off));
    }
    const float mn0 = fmaxf(mx0, mr0), mn1 = fmaxf(mx1, mr1);
    const float f0 = __expf(mx0 - mn0), f1 = __expf(mx1 - mn1);
    float rs0 = 0.f, rs1 = 0.f;
#pragma unroll
    for (int j = 0; j < 8; j++) {
      sacc[j][0] = __expf(sacc[j][0] - mn0);
      sacc[j][1] = __expf(sacc[j][1] - mn0);
      sacc[j][2] = __expf(sacc[j][2] - mn1);
      sacc[j][3] = __expf(sacc[j][3] - mn1);
      rs0 += sacc[j][0] + sacc[j][1];
      rs1 += sacc[j][2] + sacc[j][3];
    }
#pragma unroll
    for (int off = 1; off <= 2; off <<= 1) {
      rs0 += __shfl_xor_sync(0xffffffffu, rs0, off);
      rs1 += __shfl_xor_sync(0xffffffffu, rs1, off);
    }
    lr0 = lr0 * f0 + rs0; mx0 = mn0;
    lr1 = lr1 * f1 + rs1; mx1 = mn1;
#pragma unroll
    for (int nt = 0; nt < 8; nt++) {
      O[nt][0] *= f0; O[nt][1] *= f0; O[nt][2] *= f1; O[nt][3] *= f1;
    }

    // ---- O += P V (3-pass split)
#pragma unroll
    for (int kc = 0; kc < 4; kc++) {
      uint32_t ah[4], al[4];
      split2(sacc[2*kc][0],   sacc[2*kc][1],   ah[0], al[0]);
      split2(sacc[2*kc][2],   sacc[2*kc][3],   ah[1], al[1]);
      split2(sacc[2*kc+1][0], sacc[2*kc+1][1], ah[2], al[2]);
      split2(sacc[2*kc+1][2], sacc[2*kc+1][3], ah[3], al[3]);
      const uint32_t vrow = vbase + soff + kc * 16 * 144;
#pragma unroll
      for (int np = 0; np < 4; np++) {
        uint32_t vh0, vh1, vh2, vh3, vl0, vl1, vl2, vl3;
        LDMX4T(vh0, vh1, vh2, vh3, vrow + np * 32);
        LDMX4T(vl0, vl1, vl2, vl3, vrow + np * 32 + SKB);
        HMMA16816(O[2*np],   ah[0], ah[1], ah[2], ah[3], vh0, vh1);
        HMMA16816(O[2*np],   ah[0], ah[1], ah[2], ah[3], vl0, vl1);
        HMMA16816(O[2*np],   al[0], al[1], al[2], al[3], vh0, vh1);
        HMMA16816(O[2*np+1], ah[0], ah[1], ah[2], ah[3], vh2, vh3);
        HMMA16816(O[2*np+1], ah[0], ah[1], ah[2], ah[3], vl2, vl3);
        HMMA16816(O[2*np+1], al[0], al[1], al[2], al[3], vh2, vh3);
      }
    }
    __syncthreads();
  }

  // ---- epilogue: normalize, split to hi/lo bf16, store
  const float inv0 = 1.f / lr0, inv1 = 1.f / lr1;
  const size_t o0 = (size_t)(b * TT + grow) * EE + h * DH + 2 * tg;
#pragma unroll
  for (int nt = 0; nt < 8; nt++) {
    uint32_t h0, l0, h1, l1;
    split2(O[nt][0] * inv0, O[nt][1] * inv0, h0, l0);
    split2(O[nt][2] * inv1, O[nt][3] * inv1, h1, l1);
    *(uint32_t*)(aoh + o0 + nt * 8)          = h0;
    *(uint32_t*)(aol + o0 + nt * 8)          = l0;
    *(uint32_t*)(aoh + o0 + 8 * EE + nt * 8) = h1;
    *(uint32_t*)(aol + o0 + 8 * EE + nt * 8) = l1;
  }
}

// ---------------------------------------------------------------------------
// fp32 -> bf16 hi/lo split (x input)
// ---------------------------------------------------------------------------
__global__ __launch_bounds__(256) void convert_split_kernel(
    const float4* __restrict__ in, ushort4* __restrict__ hi,
    ushort4* __restrict__ lo, int n4) {
  const int i = blockIdx.x * 256 + threadIdx.x;
  if (i >= n4) return;
  const float4 v = in[i];
  ushort4 h, l;
  __nv_bfloat16 t;
  t = __float2bfloat16(v.x); h.x = __bfloat16_as_ushort(t);
  l.x = __bfloat16_as_ushort(__float2bfloat16(v.x - __bfloat162float(t)));
  t = __float2bfloat16(v.y); h.y = __bfloat16_as_ushort(t);
  l.y = __bfloat16_as_ushort(__float2bfloat16(v.y - __bfloat162float(t)));
  t = __float2bfloat16(v.z); h.z = __bfloat16_as_ushort(t);
  l.z = __bfloat16_as_ushort(__float2bfloat16(v.z - __bfloat162float(t)));
  t = __float2bfloat16(v.w); h.w = __bfloat16_as_ushort(t);
  l.w = __bfloat16_as_ushort(__float2bfloat16(v.w - __bfloat162float(t)));
  hi[i] = h; lo[i] = l;
}

// ---------------------------------------------------------------------------
// All 4 weights: W[K,N] fp32 -> W^T hi/lo [N,K] bf16 (blockIdx.z selects W)
// ---------------------------------------------------------------------------
__global__ __launch_bounds__(256) void transpose_split4_kernel(
    const float* __restrict__ W0, const float* __restrict__ W1,
    const float* __restrict__ W2, const float* __restrict__ W3,
    __nv_bfloat16* __restrict__ th, __nv_bfloat16* __restrict__ tl) {
  __shared__ float t[32][33];
  const int w = blockIdx.z;
  const float* W = (w == 0) ? W0 : (w == 1) ? W1 : (w == 2) ? W2 : W3;
  __nv_bfloat16* thw = th + (size_t)w * EE * EE;
  __nv_bfloat16* tlw = tl + (size_t)w * EE * EE;
  const int n0 = blockIdx.x * 32, k0 = blockIdx.y * 32;
  const int tx = threadIdx.x & 31, ty = threadIdx.x >> 5;
  for (int r = ty; r < 32; r += 8)
    t[r][tx] = W[(size_t)(k0 + r) * EE + n0 + tx];
  __syncthreads();
  for (int r = ty; r < 32; r += 8) {
    const float v = t[tx][r];
    const __nv_bfloat16 hh = __float2bfloat16(v);
    thw[(size_t)(n0 + r) * EE + k0 + tx] = hh;
    tlw[(size_t)(n0 + r) * EE + k0 + tx] = __float2bfloat16(v - __bfloat162float(hh));
  }
}

// ---------------------------------------------------------------------------
extern "C" void kernel_launch(void* const* d_in, const int* in_sizes, int n_in,
                              void* d_out, int out_size) {
  const float* x  = (const float*)d_in[0];
  const float* Wq = (const float*)d_in[1];
  const float* Wk = (const float*)d_in[2];
  const float* Wv = (const float*)d_in[3];
  const float* Wo = (const float*)d_in[4];
  const float* bo = (const float*)d_in[5];
  float* out = (float*)d_out;

  __nv_bfloat16 *xh, *xl, *qkvh, *qkvl, *aoh, *aol, *wth, *wtl;
  cudaGetSymbolAddress((void**)&xh,   g_xh);
  cudaGetSymbolAddress((void**)&xl,   g_xl);
  cudaGetSymbolAddress((void**)&qkvh, g_qkvh);
  cudaGetSymbolAddress((void**)&qkvl, g_qkvl);
  cudaGetSymbolAddress((void**)&aoh,  g_aoh);
  cudaGetSymbolAddress((void**)&aol,  g_aol);
  cudaGetSymbolAddress((void**)&wth,  g_wth);
  cudaGetSymbolAddress((void**)&wtl,  g_wtl);

  cudaFuncSetAttribute(mm_hmma,
                       cudaFuncAttributeMaxDynamicSharedMemorySize, MM_SMEM);
  cudaFuncSetAttribute(attn_hmma,
                       cudaFuncAttributeMaxDynamicSharedMemorySize, ATT_SMEM);

  // 1) split x; transpose+split all weights in one launch
  convert_split_kernel<<<(MROWS*EE/4 + 255)/256, 256>>>(
      (const float4*)x, (ushort4*)xh, (ushort4*)xl, MROWS*EE/4);
  dim3 tgrid(EE/32, EE/32, 4);
  transpose_split4_kernel<<<tgrid, 256>>>(Wq, Wk, Wv, Wo, wth, wtl);

  // 2) fused QKV projection (N=3072), epilogue writes bf16 hi/lo
  dim3 qgrid(3*EE/128, MROWS/128);   // (24, 32)
  mm_hmma<<<qgrid, 256, MM_SMEM>>>(xh, xl, wth, wtl, nullptr, nullptr, qkvh, qkvl);

  // 3) HMMA flash attention (double-buffered) -> aoh/aol
  dim3 agrid(TT/128, HH, BB);        // (16, 16, 2)
  attn_hmma<<<agrid, 256, ATT_SMEM>>>(qkvh, qkvl, aoh, aol);

  // 4) output projection (fp32 + bias)
  dim3 ogrid(EE/128, MROWS/128);     // (8, 32)
  mm_hmma<<<ogrid, 256, MM_SMEM>>>(aoh, aol, wth + 3*(size_t)EE*EE, wtl + 3*(size_t)EE*EE,
                                   out, bo, nullptr, nullptr);
}